// round 4
// baseline (speedup 1.0000x reference)
#include <cuda_runtime.h>

#define BB 4
#define SS 4096
#define DD 1024
#define HH 16
#define HD 64
#define BH (BB*HH)          // 64
#define CHUNKS 16           // S-chunks per (b,h) in kv kernel
#define CHUNK_S (SS/CHUNKS) // 256

// Scratch (no cudaMalloc allowed): KV summary [b][h][d][e] and k_reduced [b][h][d]
__device__ float g_kv[BH * HD * HD];    // 262144 floats, 1 MB
__device__ float g_kred[BH * HD];       // 4096 floats

// feat(x) = (tanh(x)+1)/2 == sigmoid(2x) = 1/(1+exp(-2x))
__device__ __forceinline__ float featf(float x) {
    return __fdividef(1.0f, 1.0f + __expf(-2.0f * x));
}

// Packed dual fp32 FMA (Blackwell f32x2) — 2x FFMA issue throughput
__device__ __forceinline__ float2 ffma2(float2 a, float2 b, float2 c) {
    unsigned long long au = *reinterpret_cast<unsigned long long*>(&a);
    unsigned long long bu = *reinterpret_cast<unsigned long long*>(&b);
    unsigned long long cu = *reinterpret_cast<unsigned long long*>(&c);
    unsigned long long du;
    asm("fma.rn.f32x2 %0, %1, %2, %3;" : "=l"(du) : "l"(au), "l"(bu), "l"(cu));
    return *reinterpret_cast<float2*>(&du);
}

__global__ __launch_bounds__(256) void mhi_zero_kernel() {
    int i = blockIdx.x * 256 + threadIdx.x;        // grid 1024*256 = 262144
    g_kv[i] = 0.0f;
    if (i < BH * HD) g_kred[i] = 0.0f;
}

// Kernel 1: KV[b,h,d,e] += sum_s feat(k)[s,d] * v[s,e]; k_reduced += sum_s feat(k)[s,d]
// grid = BH*CHUNKS = 1024 blocks, 256 threads
// Software-pipelined: next 16-row tile is prefetched into registers while the
// current tile is consumed from shared, hiding LDG latency under the FMA body.
__global__ __launch_bounds__(256) void mhi_kv_kernel(const float* __restrict__ kp,
                                                     const float* __restrict__ vp) {
    const int bh    = blockIdx.x / CHUNKS;
    const int chunk = blockIdx.x % CHUNKS;
    const int b = bh / HH, h = bh % HH;
    const int tid = threadIdx.x;

    // loader mapping: one float4 per thread per 16-row tile
    const int c4   = tid & 15;   // d-col group (4 floats)
    const int srow = tid >> 4;   // row within tile (0..15)
    // compute mapping: 4(d) x 4(e) register tile
    const int tx = tid & 15, ty = tid >> 4;
    const int e0 = tx * 4, d0 = ty * 4;

    __shared__ float ksh[16][64];
    __shared__ float vsh[16][64];
    __shared__ float kredsh[64];

    if (tid < 64) kredsh[tid] = 0.0f;

    float2 acc[4][2];
    #pragma unroll
    for (int i = 0; i < 4; ++i) { acc[i][0] = make_float2(0.f,0.f); acc[i][1] = make_float2(0.f,0.f); }
    float4 kred_l = make_float4(0.f,0.f,0.f,0.f);

    const long long rowbase = (long long)b * SS * DD + (long long)h * HD + c4 * 4;
    const float* kbase = kp + rowbase;
    const float* vbase = vp + rowbase;
    const int s_base = chunk * CHUNK_S;
    const int NT = CHUNK_S / 16;   // 16 tiles

    // prefetch tile 0
    float4 kq = *(const float4*)(kbase + (long long)(s_base + srow) * DD);
    float4 vq = *(const float4*)(vbase + (long long)(s_base + srow) * DD);

    for (int t = 0; t < NT; ++t) {
        // feature map + local k-reduction on the tile we are about to publish
        float4 kf;
        kf.x = featf(kq.x); kf.y = featf(kq.y); kf.z = featf(kq.z); kf.w = featf(kq.w);
        kred_l.x += kf.x; kred_l.y += kf.y; kred_l.z += kf.z; kred_l.w += kf.w;

        __syncthreads();   // previous tile's compute done before overwrite
        *(float4*)&ksh[srow][c4 * 4] = kf;
        *(float4*)&vsh[srow][c4 * 4] = vq;
        __syncthreads();

        // prefetch NEXT tile while computing on the current one
        if (t + 1 < NT) {
            const long long sg = s_base + (t + 1) * 16 + srow;
            kq = *(const float4*)(kbase + sg * DD);
            vq = *(const float4*)(vbase + sg * DD);
        }

        #pragma unroll
        for (int s = 0; s < 16; ++s) {
            float4 kk = *(const float4*)&ksh[s][d0];
            const float2* vr = (const float2*)&vsh[s][e0];
            float2 v0 = vr[0], v1 = vr[1];
            float ks4[4] = {kk.x, kk.y, kk.z, kk.w};
            #pragma unroll
            for (int i = 0; i < 4; ++i) {
                float2 kb = make_float2(ks4[i], ks4[i]);
                acc[i][0] = ffma2(kb, v0, acc[i][0]);
                acc[i][1] = ffma2(kb, v1, acc[i][1]);
            }
        }
    }

    // k_reduced: shared reduce then one global atomic per d
    atomicAdd(&kredsh[c4 * 4 + 0], kred_l.x);
    atomicAdd(&kredsh[c4 * 4 + 1], kred_l.y);
    atomicAdd(&kredsh[c4 * 4 + 2], kred_l.z);
    atomicAdd(&kredsh[c4 * 4 + 3], kred_l.w);
    __syncthreads();
    if (tid < 64) atomicAdd(&g_kred[bh * HD + tid], kredsh[tid]);

    // KV accumulation: 16 global atomics per thread
    float* kvg = g_kv + bh * HD * HD + d0 * HD + e0;
    #pragma unroll
    for (int i = 0; i < 4; ++i) {
        atomicAdd(&kvg[i * HD + 0], acc[i][0].x);
        atomicAdd(&kvg[i * HD + 1], acc[i][0].y);
        atomicAdd(&kvg[i * HD + 2], acc[i][1].x);
        atomicAdd(&kvg[i * HD + 3], acc[i][1].y);
    }
}

// Kernel 2: out[s,e] = z[s] * sum_d feat(q)[s,d] * KV[d,e],  z = 1/(feat(q).k_reduced)
// grid = BH * (S/64) = 4096 blocks, 256 threads; 64(s) x 64(e) tile per block
__global__ __launch_bounds__(256) void mhi_out_kernel(const float* __restrict__ qp,
                                                      float* __restrict__ op) {
    const int bh = blockIdx.x >> 6;
    const int st = blockIdx.x & 63;
    const int b = bh >> 4, h = bh & 15;
    const int tid = threadIdx.x;

    __shared__ float qT[64][68];     // transposed feat(q): [d][s], padded
    __shared__ float kvsh[64 * 64];  // [d][e]
    __shared__ float kredsh[64];
    __shared__ float zsh[64];

    // load KV tile (1024 float4, 4 per thread)
    {
        const float4* src = (const float4*)(g_kv + bh * HD * HD);
        float4* dst = (float4*)kvsh;
        #pragma unroll
        for (int r = 0; r < 4; ++r) dst[tid + r * 256] = src[tid + r * 256];
    }
    if (tid < 64) kredsh[tid] = g_kred[bh * HD + tid] + 1e-8f;

    // load q tile, apply feat, store transposed
    {
        const int c4 = tid & 15, sr = tid >> 4;
        const float* qbase = qp + ((long long)(b * SS + st * 64)) * DD + h * HD;
        #pragma unroll
        for (int r = 0; r < 4; ++r) {
            int s = sr + r * 16;
            float4 qq = *(const float4*)(qbase + (long long)s * DD + c4 * 4);
            qq.x = featf(qq.x); qq.y = featf(qq.y); qq.z = featf(qq.z); qq.w = featf(qq.w);
            qT[c4 * 4 + 0][s] = qq.x;
            qT[c4 * 4 + 1][s] = qq.y;
            qT[c4 * 4 + 2][s] = qq.z;
            qT[c4 * 4 + 3][s] = qq.w;
        }
    }
    __syncthreads();

    // normalizer z per s-row
    if (tid < 64) {
        float sum = 0.0f;
        #pragma unroll 8
        for (int dd = 0; dd < 64; ++dd) sum += qT[dd][tid] * kredsh[dd];
        zsh[tid] = __fdividef(1.0f, sum);
    }
    __syncthreads();

    // GEMM: 4(s) x 4(e) register tile per thread
    const int tx = tid & 15, ty = tid >> 4;
    const int e0 = tx * 4, s0 = ty * 4;
    float2 acc[4][2];
    #pragma unroll
    for (int i = 0; i < 4; ++i) { acc[i][0] = make_float2(0.f,0.f); acc[i][1] = make_float2(0.f,0.f); }

    #pragma unroll 8
    for (int dd = 0; dd < 64; ++dd) {
        float4 qv = *(const float4*)&qT[dd][s0];
        const float2* kr = (const float2*)&kvsh[dd * 64 + e0];
        float2 k0 = kr[0], k1 = kr[1];
        float qs[4] = {qv.x, qv.y, qv.z, qv.w};
        #pragma unroll
        for (int i = 0; i < 4; ++i) {
            float2 qb = make_float2(qs[i], qs[i]);
            acc[i][0] = ffma2(qb, k0, acc[i][0]);
            acc[i][1] = ffma2(qb, k1, acc[i][1]);
        }
    }

    // epilogue: scale by z, coalesced float4 stores
    float* obase = op + ((long long)(b * SS + st * 64 + s0)) * DD + h * HD + e0;
    #pragma unroll
    for (int i = 0; i < 4; ++i) {
        float z = zsh[s0 + i];
        float4 o = make_float4(acc[i][0].x * z, acc[i][0].y * z,
                               acc[i][1].x * z, acc[i][1].y * z);
        *(float4*)(obase + (long long)i * DD) = o;
    }
}

extern "C" void kernel_launch(void* const* d_in, const int* in_sizes, int n_in,
                              void* d_out, int out_size) {
    const float* q = (const float*)d_in[0];
    const float* k = (const float*)d_in[1];
    const float* v = (const float*)d_in[2];
    float* o = (float*)d_out;

    mhi_zero_kernel<<<1024, 256>>>();
    mhi_kv_kernel<<<BH * CHUNKS, 256>>>(k, v);
    mhi_out_kernel<<<BH * (SS / 64), 256>>>(q, o);
}

// round 10
// speedup vs baseline: 1.1535x; 1.1535x over previous
#include <cuda_runtime.h>
#include <cstdint>

#define BB 4
#define SS 4096
#define DD 1024
#define HH 16
#define HD 64
#define BH (BB*HH)          // 64
#define CHUNKS 8
#define CHUNK_S (SS/CHUNKS) // 512

// Scratch: KV^T summary [bh][e][d] and k_reduced [bh][d]
__device__ float g_kvT[BH * HD * HD];   // 1 MB
__device__ float g_kred[BH * HD];

// feat(x) = (tanh(x)+1)/2 == sigmoid(2x)
__device__ __forceinline__ float featf(float x) {
    return __fdividef(1.0f, 1.0f + __expf(-2.0f * x));
}

__device__ __forceinline__ float2 ffma2(float2 a, float2 b, float2 c) {
    unsigned long long au = *reinterpret_cast<unsigned long long*>(&a);
    unsigned long long bu = *reinterpret_cast<unsigned long long*>(&b);
    unsigned long long cu = *reinterpret_cast<unsigned long long*>(&c);
    unsigned long long du;
    asm("fma.rn.f32x2 %0, %1, %2, %3;" : "=l"(du) : "l"(au), "l"(bu), "l"(cu));
    return *reinterpret_cast<float2*>(&du);
}

// pack two fp32 -> bf16x2 word; low half = f0
__device__ __forceinline__ uint32_t pack_bf16x2(float f0, float f1) {
    uint32_t w;
    asm("cvt.rn.bf16x2.f32 %0, %1, %2;" : "=r"(w) : "f"(f1), "f"(f0));
    return w;
}
__device__ __forceinline__ float bf16lo_to_f(uint32_t w) { return __uint_as_float(w << 16); }
__device__ __forceinline__ float bf16hi_to_f(uint32_t w) { return __uint_as_float(w & 0xFFFF0000u); }

// m16n8k16 bf16 MMA, fp32 accumulate (base PTX ISA — compiles on compute_103)
#define MMA16816(d, a, b0, b1)                                                  \
    asm volatile("mma.sync.aligned.m16n8k16.row.col.f32.bf16.bf16.f32 "        \
        "{%0,%1,%2,%3}, {%4,%5,%6,%7}, {%8,%9}, {%0,%1,%2,%3};"                 \
        : "+f"((d)[0]), "+f"((d)[1]), "+f"((d)[2]), "+f"((d)[3])                \
        : "r"((a)[0]), "r"((a)[1]), "r"((a)[2]), "r"((a)[3]), "r"(b0), "r"(b1))

// ---------------- zero kernel ----------------
__global__ __launch_bounds__(256) void mhi_zero_kernel() {
    int i = blockIdx.x * 256 + threadIdx.x;
    g_kvT[i] = 0.0f;
    if (i < BH * HD) g_kred[i] = 0.0f;
}

// ---------------- KV kernel (scalar, transposed output) ----------------
// grid = BH*CHUNKS = 512 blocks, 256 threads
__global__ __launch_bounds__(256) void mhi_kv_kernel(const float* __restrict__ kp,
                                                     const float* __restrict__ vp) {
    const int bh    = blockIdx.x / CHUNKS;
    const int chunk = blockIdx.x % CHUNKS;
    const int b = bh / HH, h = bh % HH;
    const int tid = threadIdx.x;

    const int c4   = tid & 15;
    const int srow = tid >> 4;
    const int tx = tid & 15, ty = tid >> 4;
    const int e0 = tx * 4, d0 = ty * 4;

    __shared__ float ksh[16][64];
    __shared__ float vsh[16][64];
    __shared__ float kredsh[64];

    if (tid < 64) kredsh[tid] = 0.0f;

    float2 acc[4][2];
    #pragma unroll
    for (int i = 0; i < 4; ++i) { acc[i][0] = make_float2(0.f,0.f); acc[i][1] = make_float2(0.f,0.f); }
    float4 kred_l = make_float4(0.f,0.f,0.f,0.f);

    const long long rowbase = (long long)b * SS * DD + (long long)h * HD + c4 * 4;
    const float* kbase = kp + rowbase;
    const float* vbase = vp + rowbase;
    const int s_base = chunk * CHUNK_S;
    const int NT = CHUNK_S / 16;   // 32 tiles

    float4 kq = *(const float4*)(kbase + (long long)(s_base + srow) * DD);
    float4 vq = *(const float4*)(vbase + (long long)(s_base + srow) * DD);

    for (int t = 0; t < NT; ++t) {
        float4 kf;
        kf.x = featf(kq.x); kf.y = featf(kq.y); kf.z = featf(kq.z); kf.w = featf(kq.w);
        kred_l.x += kf.x; kred_l.y += kf.y; kred_l.z += kf.z; kred_l.w += kf.w;

        __syncthreads();
        *(float4*)&ksh[srow][c4 * 4] = kf;
        *(float4*)&vsh[srow][c4 * 4] = vq;
        __syncthreads();

        if (t + 1 < NT) {
            const long long sg = s_base + (t + 1) * 16 + srow;
            kq = *(const float4*)(kbase + sg * DD);
            vq = *(const float4*)(vbase + sg * DD);
        }

        #pragma unroll
        for (int s = 0; s < 16; ++s) {
            float4 kk = *(const float4*)&ksh[s][d0];
            const float2* vr = (const float2*)&vsh[s][e0];
            float2 v0 = vr[0], v1 = vr[1];
            float ks4[4] = {kk.x, kk.y, kk.z, kk.w};
            #pragma unroll
            for (int i = 0; i < 4; ++i) {
                float2 kb = make_float2(ks4[i], ks4[i]);
                acc[i][0] = ffma2(kb, v0, acc[i][0]);
                acc[i][1] = ffma2(kb, v1, acc[i][1]);
            }
        }
    }

    atomicAdd(&kredsh[c4 * 4 + 0], kred_l.x);
    atomicAdd(&kredsh[c4 * 4 + 1], kred_l.y);
    atomicAdd(&kredsh[c4 * 4 + 2], kred_l.z);
    atomicAdd(&kredsh[c4 * 4 + 3], kred_l.w);
    __syncthreads();
    if (tid < 64) atomicAdd(&g_kred[bh * HD + tid], kredsh[tid]);

    // TRANSPOSED accumulation into g_kvT[bh][e][d]
    float* kvg = g_kvT + bh * HD * HD;
    #pragma unroll
    for (int i = 0; i < 4; ++i) {
        int d = d0 + i;
        atomicAdd(&kvg[(e0 + 0) * HD + d], acc[i][0].x);
        atomicAdd(&kvg[(e0 + 1) * HD + d], acc[i][0].y);
        atomicAdd(&kvg[(e0 + 2) * HD + d], acc[i][1].x);
        atomicAdd(&kvg[(e0 + 3) * HD + d], acc[i][1].y);
    }
}

// ---------------- OUT kernel: mma.sync bf16, 3-term error split ----------------
// Per block: 128 s-rows x 64 e for one (b,h).  grid = BH*32 = 2048 blocks, 128 threads.
// Smem word layout (stride 36 words per logical row -> conflict-free frag loads):
#define QW     36
#define OFF_QHI  0
#define OFF_QLO  4608          // 128*36
#define OFF_KVH  9216
#define OFF_KVL  11520         // + 64*36
#define OFF_ZSH  13824
#define OFF_KRED 13952
#define SMEM_WORDS 14016       // 56064 bytes

__global__ __launch_bounds__(128) void mhi_out_mma_kernel(const float* __restrict__ qp,
                                                          float* __restrict__ op) {
    extern __shared__ uint32_t dsm[];
    const int tid = threadIdx.x;
    const int wid = tid >> 5, lid = tid & 31;
    const int bh = blockIdx.x >> 5;
    const int st = blockIdx.x & 31;
    const int b = bh >> 4, h = bh & 15;

    uint32_t* QHI = dsm + OFF_QHI;
    uint32_t* QLO = dsm + OFF_QLO;
    uint32_t* KVH = dsm + OFF_KVH;
    uint32_t* KVL = dsm + OFF_KVL;
    float* zsh    = (float*)(dsm + OFF_ZSH);
    float* kredsh = (float*)(dsm + OFF_KRED);

    if (tid < 64) kredsh[tid] = g_kred[bh * HD + tid] + 1e-8f;
    __syncthreads();

    // ---- pack KV^T[e][d] -> bf16 hi/lo smem ----
    {
        const int e = tid >> 1, half = tid & 1;
        const float4* src = (const float4*)(g_kvT + bh * HD * HD + e * HD + half * 32);
        #pragma unroll
        for (int i = 0; i < 8; ++i) {
            float4 f = src[i];
            uint32_t h0 = pack_bf16x2(f.x, f.y);
            uint32_t h1 = pack_bf16x2(f.z, f.w);
            uint32_t l0 = pack_bf16x2(f.x - bf16lo_to_f(h0), f.y - bf16hi_to_f(h0));
            uint32_t l1 = pack_bf16x2(f.z - bf16lo_to_f(h1), f.w - bf16hi_to_f(h1));
            int w = e * QW + half * 16 + i * 2;
            KVH[w] = h0; KVH[w + 1] = h1;
            KVL[w] = l0; KVL[w + 1] = l1;
        }
    }

    // ---- pack featQ[s][d] -> bf16 hi/lo smem + z-dot via half-warp shuffle ----
    {
        const int c4 = tid & 15, sr = tid >> 4;
        const float* qbase = qp + ((long long)(b * SS + st * 128)) * DD + h * HD;
        float kr0 = kredsh[c4 * 4 + 0], kr1 = kredsh[c4 * 4 + 1];
        float kr2 = kredsh[c4 * 4 + 2], kr3 = kredsh[c4 * 4 + 3];
        #pragma unroll
        for (int p = 0; p < 16; ++p) {
            const int s = p * 8 + sr;
            float4 f = *(const float4*)(qbase + (long long)s * DD + c4 * 4);
            f.x = featf(f.x); f.y = featf(f.y); f.z = featf(f.z); f.w = featf(f.w);
            float pd = f.x * kr0 + f.y * kr1 + f.z * kr2 + f.w * kr3;
            pd += __shfl_xor_sync(0xFFFFFFFFu, pd, 1);
            pd += __shfl_xor_sync(0xFFFFFFFFu, pd, 2);
            pd += __shfl_xor_sync(0xFFFFFFFFu, pd, 4);
            pd += __shfl_xor_sync(0xFFFFFFFFu, pd, 8);
            if ((lid & 15) == 0) zsh[s] = pd;
            uint32_t h0 = pack_bf16x2(f.x, f.y);
            uint32_t h1 = pack_bf16x2(f.z, f.w);
            uint32_t l0 = pack_bf16x2(f.x - bf16lo_to_f(h0), f.y - bf16hi_to_f(h0));
            uint32_t l1 = pack_bf16x2(f.z - bf16lo_to_f(h1), f.w - bf16hi_to_f(h1));
            int w = s * QW + c4 * 2;
            QHI[w] = h0; QHI[w + 1] = h1;
            QLO[w] = l0; QLO[w + 1] = l1;
        }
    }
    __syncthreads();

    // ---- MMA mainloop: warp w covers s [w*32, w*32+32), all 64 e ----
    float acc[2][8][4];
    #pragma unroll
    for (int mt = 0; mt < 2; ++mt)
        #pragma unroll
        for (int nt = 0; nt < 8; ++nt)
            #pragma unroll
            for (int i = 0; i < 4; ++i) acc[mt][nt][i] = 0.0f;

    const int r = lid >> 2, cq = lid & 3;

    #pragma unroll
    for (int kt = 0; kt < 4; ++kt) {
        uint32_t ah[2][4], al[2][4];
        #pragma unroll
        for (int mt = 0; mt < 2; ++mt) {
            const int s0 = wid * 32 + mt * 16;
            const int w0 = (s0 + r) * QW + kt * 8 + cq;
            const int w8 = (s0 + r + 8) * QW + kt * 8 + cq;
            ah[mt][0] = QHI[w0]; ah[mt][1] = QHI[w8];
            ah[mt][2] = QHI[w0 + 4]; ah[mt][3] = QHI[w8 + 4];
            al[mt][0] = QLO[w0]; al[mt][1] = QLO[w8];
            al[mt][2] = QLO[w0 + 4]; al[mt][3] = QLO[w8 + 4];
        }
        #pragma unroll
        for (int nt = 0; nt < 8; ++nt) {
            const int wb = (nt * 8 + r) * QW + kt * 8 + cq;
            uint32_t bh0 = KVH[wb], bh1 = KVH[wb + 4];
            uint32_t bl0 = KVL[wb], bl1 = KVL[wb + 4];
            #pragma unroll
            for (int mt = 0; mt < 2; ++mt) {
                MMA16816(acc[mt][nt], ah[mt], bh0, bh1);
                MMA16816(acc[mt][nt], ah[mt], bl0, bl1);
                MMA16816(acc[mt][nt], al[mt], bh0, bh1);
            }
        }
    }

    // ---- epilogue: z-scale + store ----
    #pragma unroll
    for (int mt = 0; mt < 2; ++mt) {
        const int s_local = wid * 32 + mt * 16 + r;
        const float z0 = __fdividef(1.0f, zsh[s_local]);
        const float z8 = __fdividef(1.0f, zsh[s_local + 8]);
        float* orow  = op + ((long long)(b * SS + st * 128 + s_local)) * DD + h * HD;
        float* orow8 = orow + 8 * DD;
        #pragma unroll
        for (int nt = 0; nt < 8; ++nt) {
            const int e = nt * 8 + cq * 2;
            *(float2*)(orow + e)  = make_float2(acc[mt][nt][0] * z0, acc[mt][nt][1] * z0);
            *(float2*)(orow8 + e) = make_float2(acc[mt][nt][2] * z8, acc[mt][nt][3] * z8);
        }
    }
}

extern "C" void kernel_launch(void* const* d_in, const int* in_sizes, int n_in,
                              void* d_out, int out_size) {
    const float* q = (const float*)d_in[0];
    const float* k = (const float*)d_in[1];
    const float* v = (const float*)d_in[2];
    float* o = (float*)d_out;

    cudaFuncSetAttribute(mhi_out_mma_kernel, cudaFuncAttributeMaxDynamicSharedMemorySize,
                         SMEM_WORDS * 4);

    mhi_zero_kernel<<<1024, 256>>>();
    mhi_kv_kernel<<<BH * CHUNKS, 256>>>(k, v);
    mhi_out_mma_kernel<<<BH * 32, 128, SMEM_WORDS * 4>>>(q, o);
}

// round 17
// speedup vs baseline: 1.1772x; 1.0206x over previous
#include <cuda_runtime.h>
#include <cstdint>

#define BB 4
#define SS 4096
#define DD 1024
#define HH 16
#define HD 64
#define BH (BB*HH)          // 64

// Scratch: KV^T summary [bh][e][d] and k_reduced [bh][d]
__device__ float g_kvT[BH * HD * HD];   // 1 MB
__device__ float g_kred[BH * HD];

// feat(x) = (tanh(x)+1)/2 == sigmoid(2x)
__device__ __forceinline__ float featf(float x) {
    return __fdividef(1.0f, 1.0f + __expf(-2.0f * x));
}

// pack two fp32 -> bf16x2 word; low half = f0
__device__ __forceinline__ uint32_t pack_bf16x2(float f0, float f1) {
    uint32_t w;
    asm("cvt.rn.bf16x2.f32 %0, %1, %2;" : "=r"(w) : "f"(f1), "f"(f0));
    return w;
}
__device__ __forceinline__ float bf16lo_to_f(uint32_t w) { return __uint_as_float(w << 16); }
__device__ __forceinline__ float bf16hi_to_f(uint32_t w) { return __uint_as_float(w & 0xFFFF0000u); }

// m16n8k16 bf16 MMA, fp32 accumulate (base PTX ISA — compiles on compute_103)
#define MMA16816(d, a, b0, b1)                                                  \
    asm volatile("mma.sync.aligned.m16n8k16.row.col.f32.bf16.bf16.f32 "        \
        "{%0,%1,%2,%3}, {%4,%5,%6,%7}, {%8,%9}, {%0,%1,%2,%3};"                 \
        : "+f"((d)[0]), "+f"((d)[1]), "+f"((d)[2]), "+f"((d)[3])                \
        : "r"((a)[0]), "r"((a)[1]), "r"((a)[2]), "r"((a)[3]), "r"(b0), "r"(b1))

// ---------------- zero kernel ----------------
__global__ __launch_bounds__(256) void mhi_zero_kernel() {
    int i = blockIdx.x * 256 + threadIdx.x;
    g_kvT[i] = 0.0f;
    if (i < BH * HD) g_kred[i] = 0.0f;
}

// ---------------- KV kernel: mma.sync bf16, 3-term error split ----------------
// KV^T[e][d] = sum_s V[s][e] * featK[s][d]:  A = V^T (M=e), B = featK^T (N=d), K = s.
// grid = BH * KSPLIT = 512 blocks, 256 threads; each CTA covers 512 s in 8 chunks of 64.
#define KSPLIT 8
#define KSEG  (SS/KSPLIT)   // 512
#define KCH   64
#define KNCH  (KSEG/KCH)    // 8

// smem word offsets: 64 rows x stride 36 words per buffer (2304 words);
// base offsets ≡ 0/8/16/24 mod 32 to spread STS banks across buffers.
#define KV_AHI 0
#define KV_ALO 2312
#define KV_BHI 4624
#define KV_BLO 6936
#define KV_KRED 9240
#define KV_SMEM_WORDS 9304   // 37216 bytes

__global__ __launch_bounds__(256) void mhi_kv_mma_kernel(const float* __restrict__ kp,
                                                         const float* __restrict__ vp) {
    extern __shared__ uint32_t ksm[];
    const int tid = threadIdx.x;
    const int wid = tid >> 5, lid = tid & 31;
    const int bh = blockIdx.x >> 3, split = blockIdx.x & 7;
    const int b = bh >> 4, h = bh & 15;

    uint32_t* AHI = ksm + KV_AHI;   // V^T hi   rows = e
    uint32_t* ALO = ksm + KV_ALO;   // V^T lo
    uint32_t* BHI = ksm + KV_BHI;   // featK^T hi  rows = d
    uint32_t* BLO = ksm + KV_BLO;   // featK^T lo
    float* kredsh = (float*)(ksm + KV_KRED);
    if (tid < 64) kredsh[tid] = 0.0f;

    // loader mapping: 16-s tiles, thread -> (srow = tid>>4 in 0..15, c4 = tid&15)
    const int srow = tid >> 4;
    const int c4 = tid & 15;
    const long long rowbase = (long long)b * SS * DD + (long long)h * HD + c4 * 4;
    const float* kb = kp + rowbase;
    const float* vb = vp + rowbase;
    const int s0 = split * KSEG;

    // prefetch chunk 0 (4 tiles of 16 s)
    float4 kq[4], vq[4];
    #pragma unroll
    for (int j = 0; j < 4; ++j) {
        long long s = s0 + j * 16 + srow;
        kq[j] = *(const float4*)(kb + s * DD);
        vq[j] = *(const float4*)(vb + s * DD);
    }

    float acc[4][4];
    #pragma unroll
    for (int nt = 0; nt < 4; ++nt)
        #pragma unroll
        for (int i = 0; i < 4; ++i) acc[nt][i] = 0.0f;
    float4 kred_l = make_float4(0.f, 0.f, 0.f, 0.f);

    const int r = lid >> 2, cq = lid & 3;
    const int mrow = (wid & 3) * 16;   // e-tile base (A/M)
    const int nrow = (wid >> 2) * 32;  // d-half base (B/N)
    const bool low = (lid < 16);
    const int sts_row = c4 * 4;

    for (int c = 0; c < KNCH; ++c) {
        __syncthreads();   // previous chunk's MMA done reading smem
        // ---- convert + transpose-store (warp holds s-pair (2*wid, 2*wid+1)) ----
        #pragma unroll
        for (int j = 0; j < 4; ++j) {
            float4 kf;
            kf.x = featf(kq[j].x); kf.y = featf(kq[j].y);
            kf.z = featf(kq[j].z); kf.w = featf(kq[j].w);
            kred_l.x += kf.x; kred_l.y += kf.y; kred_l.z += kf.z; kred_l.w += kf.w;

            float4 ko, vo;
            ko.x = __shfl_xor_sync(0xFFFFFFFFu, kf.x, 16);
            ko.y = __shfl_xor_sync(0xFFFFFFFFu, kf.y, 16);
            ko.z = __shfl_xor_sync(0xFFFFFFFFu, kf.z, 16);
            ko.w = __shfl_xor_sync(0xFFFFFFFFu, kf.w, 16);
            vo.x = __shfl_xor_sync(0xFFFFFFFFu, vq[j].x, 16);
            vo.y = __shfl_xor_sync(0xFFFFFFFFu, vq[j].y, 16);
            vo.z = __shfl_xor_sync(0xFFFFFFFFu, vq[j].z, 16);
            vo.w = __shfl_xor_sync(0xFFFFFFFFu, vq[j].w, 16);

            // even-s / odd-s values for this lane
            float ke[4], kd[4], ve[4], vd[4];
            ke[0] = low ? kf.x : ko.x; kd[0] = low ? ko.x : kf.x;
            ke[1] = low ? kf.y : ko.y; kd[1] = low ? ko.y : kf.y;
            ke[2] = low ? kf.z : ko.z; kd[2] = low ? ko.z : kf.z;
            ke[3] = low ? kf.w : ko.w; kd[3] = low ? ko.w : kf.w;
            ve[0] = low ? vq[j].x : vo.x; vd[0] = low ? vo.x : vq[j].x;
            ve[1] = low ? vq[j].y : vo.y; vd[1] = low ? vo.y : vq[j].y;
            ve[2] = low ? vq[j].z : vo.z; vd[2] = low ? vo.z : vq[j].z;
            ve[3] = low ? vq[j].w : vo.w; vd[3] = low ? vo.w : vq[j].w;

            const int sw = j * 8 + wid;   // s-pair word column (0..31)

            // featK -> B rows d = 4c4..+3 (low lanes: HI words; high lanes: LO words)
            uint32_t* dstB = low ? BHI : BLO;
            uint32_t* dstA = low ? AHI : ALO;
            #pragma unroll
            for (int i = 0; i < 4; ++i) {
                uint32_t hk = pack_bf16x2(ke[i], kd[i]);
                uint32_t wk = hk;
                if (!low)
                    wk = pack_bf16x2(ke[i] - bf16lo_to_f(hk), kd[i] - bf16hi_to_f(hk));
                dstB[(sts_row + i) * 36 + sw] = wk;

                uint32_t hv = pack_bf16x2(ve[i], vd[i]);
                uint32_t wv = hv;
                if (!low)
                    wv = pack_bf16x2(ve[i] - bf16lo_to_f(hv), vd[i] - bf16hi_to_f(hv));
                dstA[(sts_row + i) * 36 + sw] = wv;
            }
        }
        __syncthreads();

        // prefetch next chunk while MMA runs
        if (c + 1 < KNCH) {
            #pragma unroll
            for (int j = 0; j < 4; ++j) {
                long long s = s0 + (c + 1) * KCH + j * 16 + srow;
                kq[j] = *(const float4*)(kb + s * DD);
                vq[j] = *(const float4*)(vb + s * DD);
            }
        }

        // ---- MMA: K=64 (4 kt steps), warp tile 16(e) x 32(d), 3 products ----
        #pragma unroll
        for (int kt = 0; kt < 4; ++kt) {
            uint32_t ah[4], al[4];
            const int wA0 = (mrow + r) * 36 + kt * 8 + cq;
            const int wA8 = (mrow + r + 8) * 36 + kt * 8 + cq;
            ah[0] = AHI[wA0]; ah[1] = AHI[wA8]; ah[2] = AHI[wA0 + 4]; ah[3] = AHI[wA8 + 4];
            al[0] = ALO[wA0]; al[1] = ALO[wA8]; al[2] = ALO[wA0 + 4]; al[3] = ALO[wA8 + 4];
            #pragma unroll
            for (int nt = 0; nt < 4; ++nt) {
                const int wB = (nrow + nt * 8 + r) * 36 + kt * 8 + cq;
                uint32_t bh0 = BHI[wB], bh1 = BHI[wB + 4];
                uint32_t bl0 = BLO[wB], bl1 = BLO[wB + 4];
                MMA16816(acc[nt], ah, bh0, bh1);
                MMA16816(acc[nt], ah, bl0, bl1);
                MMA16816(acc[nt], al, bh0, bh1);
            }
        }
    }

    // ---- k_reduced: shared reduce, then one global atomic per d ----
    atomicAdd(&kredsh[c4 * 4 + 0], kred_l.x);
    atomicAdd(&kredsh[c4 * 4 + 1], kred_l.y);
    atomicAdd(&kredsh[c4 * 4 + 2], kred_l.z);
    atomicAdd(&kredsh[c4 * 4 + 3], kred_l.w);
    __syncthreads();
    if (tid < 64) atomicAdd(&g_kred[bh * HD + tid], kredsh[tid]);

    // ---- D accumulate into g_kvT[e][d]: e = mrow + r(+8), d = nrow + nt*8 + 2cq(+1) ----
    float* kvg = g_kvT + bh * HD * HD;
    #pragma unroll
    for (int nt = 0; nt < 4; ++nt) {
        const int d = nrow + nt * 8 + cq * 2;
        atomicAdd(&kvg[(mrow + r) * HD + d],         acc[nt][0]);
        atomicAdd(&kvg[(mrow + r) * HD + d + 1],     acc[nt][1]);
        atomicAdd(&kvg[(mrow + r + 8) * HD + d],     acc[nt][2]);
        atomicAdd(&kvg[(mrow + r + 8) * HD + d + 1], acc[nt][3]);
    }
}

// ---------------- OUT kernel: mma.sync bf16, 3-term error split (unchanged, verified) ----------------
#define QW     36
#define OFF_QHI  0
#define OFF_QLO  4608          // 128*36
#define OFF_KVH  9216
#define OFF_KVL  11520         // + 64*36
#define OFF_ZSH  13824
#define OFF_KRED 13952
#define SMEM_WORDS 14016       // 56064 bytes

__global__ __launch_bounds__(128) void mhi_out_mma_kernel(const float* __restrict__ qp,
                                                          float* __restrict__ op) {
    extern __shared__ uint32_t dsm[];
    const int tid = threadIdx.x;
    const int wid = tid >> 5, lid = tid & 31;
    const int bh = blockIdx.x >> 5;
    const int st = blockIdx.x & 31;
    const int b = bh >> 4, h = bh & 15;

    uint32_t* QHI = dsm + OFF_QHI;
    uint32_t* QLO = dsm + OFF_QLO;
    uint32_t* KVH = dsm + OFF_KVH;
    uint32_t* KVL = dsm + OFF_KVL;
    float* zsh    = (float*)(dsm + OFF_ZSH);
    float* kredsh = (float*)(dsm + OFF_KRED);

    if (tid < 64) kredsh[tid] = g_kred[bh * HD + tid] + 1e-8f;
    __syncthreads();

    // ---- pack KV^T[e][d] -> bf16 hi/lo smem ----
    {
        const int e = tid >> 1, half = tid & 1;
        const float4* src = (const float4*)(g_kvT + bh * HD * HD + e * HD + half * 32);
        #pragma unroll
        for (int i = 0; i < 8; ++i) {
            float4 f = src[i];
            uint32_t h0 = pack_bf16x2(f.x, f.y);
            uint32_t h1 = pack_bf16x2(f.z, f.w);
            uint32_t l0 = pack_bf16x2(f.x - bf16lo_to_f(h0), f.y - bf16hi_to_f(h0));
            uint32_t l1 = pack_bf16x2(f.z - bf16lo_to_f(h1), f.w - bf16hi_to_f(h1));
            int w = e * QW + half * 16 + i * 2;
            KVH[w] = h0; KVH[w + 1] = h1;
            KVL[w] = l0; KVL[w + 1] = l1;
        }
    }

    // ---- pack featQ[s][d] -> bf16 hi/lo smem + z-dot via half-warp shuffle ----
    {
        const int c4 = tid & 15, sr = tid >> 4;
        const float* qbase = qp + ((long long)(b * SS + st * 128)) * DD + h * HD;
        float kr0 = kredsh[c4 * 4 + 0], kr1 = kredsh[c4 * 4 + 1];
        float kr2 = kredsh[c4 * 4 + 2], kr3 = kredsh[c4 * 4 + 3];
        #pragma unroll
        for (int p = 0; p < 16; ++p) {
            const int s = p * 8 + sr;
            float4 f = *(const float4*)(qbase + (long long)s * DD + c4 * 4);
            f.x = featf(f.x); f.y = featf(f.y); f.z = featf(f.z); f.w = featf(f.w);
            float pd = f.x * kr0 + f.y * kr1 + f.z * kr2 + f.w * kr3;
            pd += __shfl_xor_sync(0xFFFFFFFFu, pd, 1);
            pd += __shfl_xor_sync(0xFFFFFFFFu, pd, 2);
            pd += __shfl_xor_sync(0xFFFFFFFFu, pd, 4);
            pd += __shfl_xor_sync(0xFFFFFFFFu, pd, 8);
            if ((lid & 15) == 0) zsh[s] = pd;
            uint32_t h0 = pack_bf16x2(f.x, f.y);
            uint32_t h1 = pack_bf16x2(f.z, f.w);
            uint32_t l0 = pack_bf16x2(f.x - bf16lo_to_f(h0), f.y - bf16hi_to_f(h0));
            uint32_t l1 = pack_bf16x2(f.z - bf16lo_to_f(h1), f.w - bf16hi_to_f(h1));
            int w = s * QW + c4 * 2;
            QHI[w] = h0; QHI[w + 1] = h1;
            QLO[w] = l0; QLO[w + 1] = l1;
        }
    }
    __syncthreads();

    // ---- MMA mainloop: warp w covers s [w*32, w*32+32), all 64 e ----
    float acc[2][8][4];
    #pragma unroll
    for (int mt = 0; mt < 2; ++mt)
        #pragma unroll
        for (int nt = 0; nt < 8; ++nt)
            #pragma unroll
            for (int i = 0; i < 4; ++i) acc[mt][nt][i] = 0.0f;

    const int r = lid >> 2, cq = lid & 3;

    #pragma unroll
    for (int kt = 0; kt < 4; ++kt) {
        uint32_t ah[2][4], al[2][4];
        #pragma unroll
        for (int mt = 0; mt < 2; ++mt) {
            const int s0 = wid * 32 + mt * 16;
            const int w0 = (s0 + r) * QW + kt * 8 + cq;
            const int w8 = (s0 + r + 8) * QW + kt * 8 + cq;
            ah[mt][0] = QHI[w0]; ah[mt][1] = QHI[w8];
            ah[mt][2] = QHI[w0 + 4]; ah[mt][3] = QHI[w8 + 4];
            al[mt][0] = QLO[w0]; al[mt][1] = QLO[w8];
            al[mt][2] = QLO[w0 + 4]; al[mt][3] = QLO[w8 + 4];
        }
        #pragma unroll
        for (int nt = 0; nt < 8; ++nt) {
            const int wb = (nt * 8 + r) * QW + kt * 8 + cq;
            uint32_t bh0 = KVH[wb], bh1 = KVH[wb + 4];
            uint32_t bl0 = KVL[wb], bl1 = KVL[wb + 4];
            #pragma unroll
            for (int mt = 0; mt < 2; ++mt) {
                MMA16816(acc[mt][nt], ah[mt], bh0, bh1);
                MMA16816(acc[mt][nt], ah[mt], bl0, bl1);
                MMA16816(acc[mt][nt], al[mt], bh0, bh1);
            }
        }
    }

    // ---- epilogue: z-scale + store ----
    #pragma unroll
    for (int mt = 0; mt < 2; ++mt) {
        const int s_local = wid * 32 + mt * 16 + r;
        const float z0 = __fdividef(1.0f, zsh[s_local]);
        const float z8 = __fdividef(1.0f, zsh[s_local + 8]);
        float* orow  = op + ((long long)(b * SS + st * 128 + s_local)) * DD + h * HD;
        float* orow8 = orow + 8 * DD;
        #pragma unroll
        for (int nt = 0; nt < 8; ++nt) {
            const int e = nt * 8 + cq * 2;
            *(float2*)(orow + e)  = make_float2(acc[mt][nt][0] * z0, acc[mt][nt][1] * z0);
            *(float2*)(orow8 + e) = make_float2(acc[mt][nt][2] * z8, acc[mt][nt][3] * z8);
        }
    }
}

extern "C" void kernel_launch(void* const* d_in, const int* in_sizes, int n_in,
                              void* d_out, int out_size) {
    const float* q = (const float*)d_in[0];
    const float* k = (const float*)d_in[1];
    const float* v = (const float*)d_in[2];
    float* o = (float*)d_out;

    cudaFuncSetAttribute(mhi_kv_mma_kernel, cudaFuncAttributeMaxDynamicSharedMemorySize,
                         KV_SMEM_WORDS * 4);
    cudaFuncSetAttribute(mhi_out_mma_kernel, cudaFuncAttributeMaxDynamicSharedMemorySize,
                         SMEM_WORDS * 4);

    mhi_zero_kernel<<<1024, 256>>>();
    mhi_kv_mma_kernel<<<BH * KSPLIT, 256, KV_SMEM_WORDS * 4>>>(k, v);
    mhi_out_mma_kernel<<<BH * 32, 128, SMEM_WORDS * 4>>>(q, o);
}